// round 2
// baseline (speedup 1.0000x reference)
#include <cuda_runtime.h>
#include <cuda_bf16.h>
#include <math_constants.h>

// Problem shape constants
#define BATCH   8
#define SEQ     2048
#define DIM     512
#define NOUT    1026          // N_FFT + 2
#define NBINS   513           // N_FFT/2 + 1
#define NFFT    1024
#define HOP     256
#define PADQ    384           // (WIN_LEN - HOP)/2
#define MROWS   (BATCH*SEQ)   // 16384
#define OUTB    524288        // per-batch output length = SEQ*HOP

// Scratch in __device__ globals (allocation-free contract)
__device__ float g_H[(size_t)MROWS * NOUT];   // h = xW + b
__device__ float g_F[(size_t)MROWS * NFFT];   // windowed irfft frames

// ---------------------------------------------------------------------------
// Kernel 1: GEMM  H[m][n] = sum_k x[m][k] * W[k][n] + b[n]
//   M = 16384, K = 512, N = 1026
//   Tile 128x64, BK=16, 256 threads, 8x4 per-thread microtile
// ---------------------------------------------------------------------------
#define BM 128
#define BN 64
#define BKK 16
#define AST 132   // padded stride for As to break store bank conflicts

__global__ __launch_bounds__(256) void gemm_kernel(
    const float* __restrict__ A,    // x  [16384,512]
    const float* __restrict__ Wm,   // W  [512,1026]
    const float* __restrict__ bias) // b  [1026]
{
    __shared__ float As[BKK * AST];
    __shared__ float Bs[BKK * BN];

    const int m0 = blockIdx.y * BM;
    const int n0 = blockIdx.x * BN;
    const int tid = threadIdx.x;
    const int tr = tid >> 4;   // 0..15  -> rows tr*8..tr*8+7
    const int tc = tid & 15;   // 0..15  -> cols tc*4..tc*4+3

    float acc[8][4];
#pragma unroll
    for (int i = 0; i < 8; i++)
#pragma unroll
        for (int j = 0; j < 4; j++) acc[i][j] = 0.f;

    for (int k0 = 0; k0 < DIM; k0 += BKK) {
        // Load A tile 128x16 as float4, store transposed As[k][m]
#pragma unroll
        for (int i = 0; i < 2; i++) {
            int v = tid + i * 256;          // 0..511
            int row = v >> 2;               // 0..127
            int c4 = (v & 3) * 4;           // 0,4,8,12
            float4 a = *reinterpret_cast<const float4*>(
                A + (size_t)(m0 + row) * DIM + k0 + c4);
            As[(c4 + 0) * AST + row] = a.x;
            As[(c4 + 1) * AST + row] = a.y;
            As[(c4 + 2) * AST + row] = a.z;
            As[(c4 + 3) * AST + row] = a.w;
        }
        // Load B tile 16x64 (scalar, bounds-checked for N tail)
#pragma unroll
        for (int i = 0; i < 4; i++) {
            int e = tid + i * 256;          // 0..1023
            int row = e >> 6;               // 0..15
            int col = e & 63;               // 0..63
            int n = n0 + col;
            Bs[row * BN + col] = (n < NOUT) ? Wm[(size_t)(k0 + row) * NOUT + n] : 0.f;
        }
        __syncthreads();

        float regM[8], regN[4];
#pragma unroll
        for (int k = 0; k < BKK; k++) {
#pragma unroll
            for (int i = 0; i < 8; i++) regM[i] = As[k * AST + tr * 8 + i];
#pragma unroll
            for (int j = 0; j < 4; j++) regN[j] = Bs[k * BN + tc * 4 + j];
#pragma unroll
            for (int i = 0; i < 8; i++)
#pragma unroll
                for (int j = 0; j < 4; j++)
                    acc[i][j] = fmaf(regM[i], regN[j], acc[i][j]);
        }
        __syncthreads();
    }

#pragma unroll
    for (int j = 0; j < 4; j++) {
        int n = n0 + tc * 4 + j;
        if (n < NOUT) {
            float bv = bias[n];
#pragma unroll
            for (int i = 0; i < 8; i++) {
                int m = m0 + tr * 8 + i;
                g_H[(size_t)m * NOUT + n] = acc[i][j] + bv;
            }
        }
    }
}

// ---------------------------------------------------------------------------
// Kernel 2: per-frame nonlinearity + irfft(1024) + Hann window
// One block (128 threads) per frame. irfft via 512-pt complex IFFT packing.
// ---------------------------------------------------------------------------
__global__ __launch_bounds__(128) void fft_kernel()
{
    __shared__ float sr[NBINS], si[NBINS];   // spectrum S_k
    __shared__ float twr[512], twi[512];     // tw[k] = e^{+2*pi*i*k/1024}
    __shared__ float zr[512], zi[512];       // packed complex sequence

    const int f = blockIdx.x;
    const int tid = threadIdx.x;
    const float* __restrict__ h = g_H + (size_t)f * NOUT;

    // Nonlinearity: mag = min(exp(h_mag),100), S = mag * e^{i p}
    for (int k = tid; k < NBINS; k += 128) {
        float mag = fminf(expf(h[k]), 100.0f);
        float p = h[NBINS + k];
        float s, c;
        sincosf(p, &s, &c);
        sr[k] = mag * c;
        si[k] = mag * s;
    }
    // Twiddle table e^{+2*pi*i*k/1024}
    const float ang = 6.283185307179586476f / 1024.0f;
    for (int k = tid; k < 512; k += 128) {
        float s, c;
        sincosf(ang * (float)k, &s, &c);
        twr[k] = c;
        twi[k] = s;
    }
    __syncthreads();

    // Packing: X_0 = Re(S_0), X_512 = Re(S_512), hermitian elsewhere.
    // E_k = (X_k + conj(X_{512-k}))/2 ; O_k = (X_k - conj(X_{512-k}))/2 * e^{+2*pi*i*k/1024}
    // Z_k = E_k + i*O_k, then z = IFFT512(Z); x[2m]=Re z_m, x[2m+1]=Im z_m.
    for (int k = tid; k < 512; k += 128) {
        float Zr, Zi;
        if (k == 0) {
            float e = 0.5f * (sr[0] + sr[512]);
            float o = 0.5f * (sr[0] - sr[512]);
            Zr = e; Zi = o;
        } else {
            float ar = sr[k],       ai = si[k];
            float br = sr[512 - k], bi = si[512 - k];
            float Er = 0.5f * (ar + br), Ei = 0.5f * (ai - bi);
            float Dr = 0.5f * (ar - br), Di = 0.5f * (ai + bi);
            float tr = twr[k], ti = twi[k];
            float Or = Dr * tr - Di * ti;
            float Oi = Dr * ti + Di * tr;
            Zr = Er - Oi;
            Zi = Ei + Or;
        }
        int r = (int)(__brev((unsigned)k) >> 23);  // 9-bit bit reversal
        zr[r] = Zr;
        zi[r] = Zi;
    }
    __syncthreads();

    // In-place radix-2 DIT inverse FFT (512 points), twiddle = e^{+2*pi*i*pos/len}
#pragma unroll
    for (int len = 2; len <= 512; len <<= 1) {
        int half = len >> 1;
        int tstep = 1024 / len;  // index multiplier into tw (tw is per 1/1024)
        for (int bf = tid; bf < 256; bf += 128) {
            int pos = bf & (half - 1);
            int i = ((bf - pos) << 1) + pos;   // (bf/half)*len + pos
            int j = i + half;
            float wr = twr[pos * tstep], wi = twi[pos * tstep];
            float xr = zr[j], xi = zi[j];
            float tr = wr * xr - wi * xi;
            float ti = wr * xi + wi * xr;
            float ur = zr[i], ui = zi[i];
            zr[i] = ur + tr; zi[i] = ui + ti;
            zr[j] = ur - tr; zi[j] = ui - ti;
        }
        __syncthreads();
    }

    // Unpack, scale 1/512, window, store
    float* __restrict__ Fo = g_F + (size_t)f * NFFT;
    const float wang = 6.283185307179586476f / 1024.0f;
    for (int m = tid; m < 512; m += 128) {
        float x0 = zr[m] * (1.0f / 512.0f);
        float x1 = zi[m] * (1.0f / 512.0f);
        int n0 = 2 * m, n1 = 2 * m + 1;
        float w0 = 0.5f * (1.0f - cosf(wang * (float)n0));
        float w1 = 0.5f * (1.0f - cosf(wang * (float)n1));
        Fo[n0] = x0 * w0;
        Fo[n1] = x1 * w1;
    }
}

// ---------------------------------------------------------------------------
// Kernel 3: overlap-add + env normalization + trim
// ---------------------------------------------------------------------------
__global__ __launch_bounds__(256) void ola_kernel(float* __restrict__ out)
{
    int o = blockIdx.x * 256 + threadIdx.x;
    if (o >= OUTB) return;
    int b = blockIdx.y;
    int t = o + PADQ;

    int jhi = min(t >> 8, SEQ - 1);
    // jlo = smallest j with t - 256*j <= 1023  ->  j >= (t-1023)/256
    int jlo = (t - 768) >> 8;
    if (jlo < 0) jlo = 0;

    const float wang = 6.283185307179586476f / 1024.0f;
    float acc = 0.f, env = 0.f;
    for (int j = jlo; j <= jhi; j++) {
        int n = t - (j << 8);
        acc += g_F[((size_t)(b * SEQ + j) << 10) + n];
        float w = 0.5f * (1.0f - cosf(wang * (float)n));
        env += w * w;
    }
    out[(size_t)b * OUTB + o] = acc / env;
}

// ---------------------------------------------------------------------------
extern "C" void kernel_launch(void* const* d_in, const int* in_sizes, int n_in,
                              void* d_out, int out_size)
{
    (void)in_sizes; (void)n_in; (void)out_size;
    const float* x    = (const float*)d_in[0];
    const float* Wm   = (const float*)d_in[1];
    const float* bias = (const float*)d_in[2];
    float* out = (float*)d_out;

    dim3 ggrid((NOUT + BN - 1) / BN, MROWS / BM);   // (17, 128)
    gemm_kernel<<<ggrid, 256>>>(x, Wm, bias);

    fft_kernel<<<MROWS, 128>>>();

    dim3 ogrid(OUTB / 256, BATCH);                  // (2048, 8)
    ola_kernel<<<ogrid, 256>>>(out);
}

// round 4
// speedup vs baseline: 1.6362x; 1.6362x over previous
#include <cuda_runtime.h>
#include <cuda_bf16.h>
#include <cstdint>

// ---------------------------------------------------------------------------
// Problem shape constants
// ---------------------------------------------------------------------------
#define BATCH   8
#define SEQ     2048
#define DIM     512
#define NOUT    1026          // N_FFT + 2
#define NBINS   513           // N_FFT/2 + 1
#define NFFT    1024
#define HOP     256
#define PADQ    384           // (WIN_LEN - HOP)/2
#define MROWS   (BATCH*SEQ)   // 16384
#define OUTB    524288        // per-batch output length = SEQ*HOP
#define NPAD    1088          // padded N (17 * 64)

// GEMM tiling
#define BMg     128
#define BNg     64
#define BKg     32
#define NCHUNK  (DIM/BKg)     // 16
// smem stage layout (bytes): Ah 10240 | Al 10240 | Bh 5120 | Bl 5120
#define OFF_AL  10240
#define OFF_BH  20480
#define OFF_BL  25600
#define STAGEB  30720
#define DYNSM   (2*STAGEB)    // 61440

// ---------------------------------------------------------------------------
// Device scratch (allocation-free contract)
// ---------------------------------------------------------------------------
__device__ float          g_H[(size_t)MROWS * NOUT];    // h = xW + b
__device__ float          g_F[(size_t)MROWS * NFFT];    // windowed irfft frames
__device__ unsigned short g_Ah[(size_t)MROWS * DIM];    // bf16 hi(x)
__device__ unsigned short g_Al[(size_t)MROWS * DIM];    // bf16 lo(x)
__device__ unsigned short g_Wth[(size_t)NPAD * DIM];    // bf16 hi(W^T) [n][k]
__device__ unsigned short g_Wtl[(size_t)NPAD * DIM];    // bf16 lo(W^T) [n][k]

// ---------------------------------------------------------------------------
// Portable PTX helpers (no sm_103a-only features!)
// ---------------------------------------------------------------------------
__device__ __forceinline__ uint32_t smem_u32(const void* p) {
    uint32_t a;
    asm("{ .reg .u64 t; cvta.to.shared.u64 t, %1; cvt.u32.u64 %0, t; }"
        : "=r"(a) : "l"(p));
    return a;
}
__device__ __forceinline__ void cp16(uint32_t dst, const void* src) {
    asm volatile("cp.async.cg.shared.global [%0], [%1], 16;"
                 :: "r"(dst), "l"(src) : "memory");
}
#define CP_COMMIT() asm volatile("cp.async.commit_group;" ::: "memory")
#define CP_WAIT1()  asm volatile("cp.async.wait_group 1;" ::: "memory")

__device__ __forceinline__ void mma16816(float* c, const uint32_t* a, const uint32_t* b) {
    asm volatile(
        "mma.sync.aligned.m16n8k16.row.col.f32.bf16.bf16.f32 "
        "{%0,%1,%2,%3}, {%4,%5,%6,%7}, {%8,%9}, {%0,%1,%2,%3};"
        : "+f"(c[0]), "+f"(c[1]), "+f"(c[2]), "+f"(c[3])
        : "r"(a[0]), "r"(a[1]), "r"(a[2]), "r"(a[3]), "r"(b[0]), "r"(b[1]));
}

// ---------------------------------------------------------------------------
// Prep kernels: fp32 -> bf16 hi/lo split (and W transpose + pad)
// ---------------------------------------------------------------------------
__device__ __forceinline__ void split_bf16(float x, unsigned short& h, unsigned short& l) {
    __nv_bfloat16 bh = __float2bfloat16(x);
    float r = x - __bfloat162float(bh);
    __nv_bfloat16 bl = __float2bfloat16(r);
    h = *reinterpret_cast<unsigned short*>(&bh);
    l = *reinterpret_cast<unsigned short*>(&bl);
}

__global__ __launch_bounds__(256) void convert_x_kernel(const float* __restrict__ x)
{
    size_t v = (size_t)blockIdx.x * 256 + threadIdx.x;   // one float4 per thread
    float4 a = *reinterpret_cast<const float4*>(x + v * 4);
    unsigned short h0,l0,h1,l1,h2,l2,h3,l3;
    split_bf16(a.x, h0, l0); split_bf16(a.y, h1, l1);
    split_bf16(a.z, h2, l2); split_bf16(a.w, h3, l3);
    uint2 hv = make_uint2((uint32_t)h0 | ((uint32_t)h1 << 16), (uint32_t)h2 | ((uint32_t)h3 << 16));
    uint2 lv = make_uint2((uint32_t)l0 | ((uint32_t)l1 << 16), (uint32_t)l2 | ((uint32_t)l3 << 16));
    *reinterpret_cast<uint2*>(g_Ah + v * 4) = hv;
    *reinterpret_cast<uint2*>(g_Al + v * 4) = lv;
}

__global__ __launch_bounds__(256) void convert_w_kernel(const float* __restrict__ W)
{
    size_t v = (size_t)blockIdx.x * 256 + threadIdx.x;   // over NPAD * (DIM/4)
    int n = (int)(v >> 7);          // 0..1087
    int k4 = ((int)v & 127) * 4;
    unsigned short h[4], l[4];
#pragma unroll
    for (int j = 0; j < 4; j++) {
        float w = (n < NOUT) ? W[(size_t)(k4 + j) * NOUT + n] : 0.0f;
        split_bf16(w, h[j], l[j]);
    }
    uint2 hv = make_uint2((uint32_t)h[0] | ((uint32_t)h[1] << 16), (uint32_t)h[2] | ((uint32_t)h[3] << 16));
    uint2 lv = make_uint2((uint32_t)l[0] | ((uint32_t)l[1] << 16), (uint32_t)l[2] | ((uint32_t)l[3] << 16));
    *reinterpret_cast<uint2*>(g_Wth + (size_t)n * DIM + k4) = hv;
    *reinterpret_cast<uint2*>(g_Wtl + (size_t)n * DIM + k4) = lv;
}

// ---------------------------------------------------------------------------
// mma.sync bf16x3 GEMM: H[m][n] = sum_k x[m][k]*W[k][n] + b[n]
//   Smem rows padded to 80B (40 halves) -> conflict-free fragment LDS.
// ---------------------------------------------------------------------------
__device__ __forceinline__ void load_stage(char* smem, int s, int kc, int tid,
                                           int m0, int n0, uint32_t smb)
{
    const uint32_t sb = smb + s * STAGEB;
    const int kk = kc * BKg;
#pragma unroll
    for (int i = 0; i < 2; i++) {
        int id = tid + i * 256;            // 0..511
        int row = id >> 2, c = id & 3;
        size_t goff = (size_t)(m0 + row) * DIM + kk + c * 8;
        cp16(sb + row * 80 + c * 16,           g_Ah + goff);
        cp16(sb + OFF_AL + row * 80 + c * 16,  g_Al + goff);
    }
    {
        int row = tid >> 2, c = tid & 3;   // row 0..63
        size_t goff = (size_t)(n0 + row) * DIM + kk + c * 8;
        cp16(sb + OFF_BH + row * 80 + c * 16,  g_Wth + goff);
        cp16(sb + OFF_BL + row * 80 + c * 16,  g_Wtl + goff);
    }
}

__global__ __launch_bounds__(256) void gemm_mma_kernel(const float* __restrict__ bias)
{
    extern __shared__ char sm[];
    const int tid  = threadIdx.x;
    const int n0   = blockIdx.x * BNg;
    const int m0   = blockIdx.y * BMg;
    const int wid  = tid >> 5, lane = tid & 31;
    const int g    = lane >> 2, t = lane & 3;
    const int wM   = (wid & 3) * 32;       // warp row offset in tile
    const int wN   = (wid >> 2) * 32;      // warp col offset in tile
    const uint32_t smb = smem_u32(sm);

    float acc[2][4][4];
#pragma unroll
    for (int i = 0; i < 2; i++)
#pragma unroll
        for (int j = 0; j < 4; j++)
#pragma unroll
            for (int q = 0; q < 4; q++) acc[i][j][q] = 0.f;

    load_stage(sm, 0, 0, tid, m0, n0, smb);
    CP_COMMIT();

    for (int kc = 0; kc < NCHUNK; kc++) {
        if (kc + 1 < NCHUNK) load_stage(sm, (kc + 1) & 1, kc + 1, tid, m0, n0, smb);
        CP_COMMIT();
        CP_WAIT1();
        __syncthreads();

        char* stg = sm + (kc & 1) * STAGEB;
#pragma unroll
        for (int ks = 0; ks < 2; ks++) {
            const int kb = ks * 16;
            uint32_t ah[2][4], al[2][4], bh[4][2], bl[4][2];
#pragma unroll
            for (int mf = 0; mf < 2; mf++) {
                int rb = wM + mf * 16;
                ah[mf][0] = *(const uint32_t*)(stg + (rb + g    ) * 80 + (kb + t * 2    ) * 2);
                ah[mf][1] = *(const uint32_t*)(stg + (rb + g + 8) * 80 + (kb + t * 2    ) * 2);
                ah[mf][2] = *(const uint32_t*)(stg + (rb + g    ) * 80 + (kb + t * 2 + 8) * 2);
                ah[mf][3] = *(const uint32_t*)(stg + (rb + g + 8) * 80 + (kb + t * 2 + 8) * 2);
            }
#pragma unroll
            for (int nf = 0; nf < 4; nf++) {
                int cb = wN + nf * 8;
                bh[nf][0] = *(const uint32_t*)(stg + OFF_BH + (cb + g) * 80 + (kb + t * 2    ) * 2);
                bh[nf][1] = *(const uint32_t*)(stg + OFF_BH + (cb + g) * 80 + (kb + t * 2 + 8) * 2);
            }
#pragma unroll
            for (int mf = 0; mf < 2; mf++)
#pragma unroll
                for (int nf = 0; nf < 4; nf++)
                    mma16816(acc[mf][nf], ah[mf], bh[nf]);

#pragma unroll
            for (int nf = 0; nf < 4; nf++) {
                int cb = wN + nf * 8;
                bl[nf][0] = *(const uint32_t*)(stg + OFF_BL + (cb + g) * 80 + (kb + t * 2    ) * 2);
                bl[nf][1] = *(const uint32_t*)(stg + OFF_BL + (cb + g) * 80 + (kb + t * 2 + 8) * 2);
            }
#pragma unroll
            for (int mf = 0; mf < 2; mf++)
#pragma unroll
                for (int nf = 0; nf < 4; nf++)
                    mma16816(acc[mf][nf], ah[mf], bl[nf]);

#pragma unroll
            for (int mf = 0; mf < 2; mf++) {
                int rb = wM + mf * 16;
                al[mf][0] = *(const uint32_t*)(stg + OFF_AL + (rb + g    ) * 80 + (kb + t * 2    ) * 2);
                al[mf][1] = *(const uint32_t*)(stg + OFF_AL + (rb + g + 8) * 80 + (kb + t * 2    ) * 2);
                al[mf][2] = *(const uint32_t*)(stg + OFF_AL + (rb + g    ) * 80 + (kb + t * 2 + 8) * 2);
                al[mf][3] = *(const uint32_t*)(stg + OFF_AL + (rb + g + 8) * 80 + (kb + t * 2 + 8) * 2);
            }
#pragma unroll
            for (int mf = 0; mf < 2; mf++)
#pragma unroll
                for (int nf = 0; nf < 4; nf++)
                    mma16816(acc[mf][nf], al[mf], bh[nf]);
        }
        __syncthreads();
    }

    // Epilogue: bias + direct stores
#pragma unroll
    for (int nf = 0; nf < 4; nf++) {
        int col = n0 + wN + nf * 8 + t * 2;
        if (col < NOUT) {
            float b0 = bias[col], b1 = bias[col + 1];
#pragma unroll
            for (int mf = 0; mf < 2; mf++) {
                int r0 = m0 + wM + mf * 16 + g;
                float2 v0 = make_float2(acc[mf][nf][0] + b0, acc[mf][nf][1] + b1);
                float2 v1 = make_float2(acc[mf][nf][2] + b0, acc[mf][nf][3] + b1);
                *reinterpret_cast<float2*>(g_H + (size_t)r0 * NOUT + col) = v0;
                *reinterpret_cast<float2*>(g_H + (size_t)(r0 + 8) * NOUT + col) = v1;
            }
        }
    }
}

// ---------------------------------------------------------------------------
// FFT kernel: nonlinearity + irfft(1024) + Hann window (one block per frame)
// ---------------------------------------------------------------------------
__global__ __launch_bounds__(256) void fft_kernel()
{
    __shared__ float sr[NBINS], si[NBINS];
    __shared__ float twr[512], twi[512];
    __shared__ float zr[512], zi[512];

    const int f = blockIdx.x;
    const int tid = threadIdx.x;
    const float* __restrict__ h = g_H + (size_t)f * NOUT;

    const float ang = 6.283185307179586476f / 1024.0f;
    for (int k = tid; k < 512; k += 256) {
        float s, c;
        __sincosf(ang * (float)k, &s, &c);
        twr[k] = c; twi[k] = s;
    }
    for (int k = tid; k < NBINS; k += 256) {
        float mag = fminf(__expf(h[k]), 100.0f);
        float p = h[NBINS + k];
        float s, c;
        __sincosf(p, &s, &c);
        sr[k] = mag * c;
        si[k] = mag * s;
    }
    __syncthreads();

    for (int k = tid; k < 512; k += 256) {
        float Zr, Zi;
        if (k == 0) {
            Zr = 0.5f * (sr[0] + sr[512]);
            Zi = 0.5f * (sr[0] - sr[512]);
        } else {
            float ar = sr[k],       ai = si[k];
            float br = sr[512 - k], bi = si[512 - k];
            float Er = 0.5f * (ar + br), Ei = 0.5f * (ai - bi);
            float Dr = 0.5f * (ar - br), Di = 0.5f * (ai + bi);
            float tr = twr[k], ti = twi[k];
            float Or = Dr * tr - Di * ti;
            float Oi = Dr * ti + Di * tr;
            Zr = Er - Oi;
            Zi = Ei + Or;
        }
        int r = (int)(__brev((unsigned)k) >> 23);
        zr[r] = Zr; zi[r] = Zi;
    }
    __syncthreads();

#pragma unroll
    for (int len = 2; len <= 512; len <<= 1) {
        int half = len >> 1;
        int tstep = 1024 / len;
        int bf = tid;
        int pos = bf & (half - 1);
        int i = ((bf - pos) << 1) + pos;
        int j = i + half;
        float wr = twr[pos * tstep], wi = twi[pos * tstep];
        float xr = zr[j], xi = zi[j];
        float tr = wr * xr - wi * xi;
        float ti = wr * xi + wi * xr;
        float ur = zr[i], ui = zi[i];
        __syncthreads();   // all reads done before writes
        zr[i] = ur + tr; zi[i] = ui + ti;
        zr[j] = ur - tr; zi[j] = ui - ti;
        __syncthreads();
    }

    float* __restrict__ Fo = g_F + (size_t)f * NFFT;
    for (int m = tid; m < 512; m += 256) {
        float x0 = zr[m] * (1.0f / 512.0f);
        float x1 = zi[m] * (1.0f / 512.0f);
        int n0 = 2 * m, n1 = 2 * m + 1;
        float w0 = 0.5f * (1.0f - __cosf(ang * (float)n0));
        float w1 = 0.5f * (1.0f - __cosf(ang * (float)n1));
        Fo[n0] = x0 * w0;
        Fo[n1] = x1 * w1;
    }
}

// ---------------------------------------------------------------------------
// Overlap-add + env normalization + trim
// ---------------------------------------------------------------------------
__global__ __launch_bounds__(256) void ola_kernel(float* __restrict__ out)
{
    int o = blockIdx.x * 256 + threadIdx.x;
    if (o >= OUTB) return;
    int b = blockIdx.y;
    int t = o + PADQ;

    int jhi = min(t >> 8, SEQ - 1);
    int jlo = (t - 768) >> 8;
    if (jlo < 0) jlo = 0;

    const float ang = 6.283185307179586476f / 1024.0f;
    float acc = 0.f, env = 0.f;
    for (int j = jlo; j <= jhi; j++) {
        int n = t - (j << 8);
        acc += g_F[((size_t)(b * SEQ + j) << 10) + n];
        float w = 0.5f * (1.0f - __cosf(ang * (float)n));
        env += w * w;
    }
    out[(size_t)b * OUTB + o] = acc / env;
}

// ---------------------------------------------------------------------------
extern "C" void kernel_launch(void* const* d_in, const int* in_sizes, int n_in,
                              void* d_out, int out_size)
{
    (void)in_sizes; (void)n_in; (void)out_size;
    const float* x    = (const float*)d_in[0];
    const float* Wm   = (const float*)d_in[1];
    const float* bias = (const float*)d_in[2];
    float* out = (float*)d_out;

    cudaFuncSetAttribute(gemm_mma_kernel, cudaFuncAttributeMaxDynamicSharedMemorySize, DYNSM);

    convert_x_kernel<<<(MROWS * DIM) / (256 * 4), 256>>>(x);
    convert_w_kernel<<<(NPAD * (DIM / 4)) / 256, 256>>>(Wm);

    dim3 ggrid(NPAD / BNg, MROWS / BMg);   // (17, 128)
    gemm_mma_kernel<<<ggrid, 256, DYNSM>>>(bias);

    fft_kernel<<<MROWS, 256>>>();

    dim3 ogrid(OUTB / 256, BATCH);
    ola_kernel<<<ogrid, 256>>>(out);
}

// round 5
// speedup vs baseline: 2.1329x; 1.3036x over previous
#include <cuda_runtime.h>
#include <cuda_bf16.h>
#include <cstdint>

// ---------------------------------------------------------------------------
// Problem shape constants
// ---------------------------------------------------------------------------
#define BATCH   8
#define SEQ     2048
#define DIM     512
#define NOUT    1026          // N_FFT + 2
#define NBINS   513           // N_FFT/2 + 1
#define NFFT    1024
#define HOP     256
#define PADQ    384           // (WIN_LEN - HOP)/2
#define MROWS   (BATCH*SEQ)   // 16384
#define OUTB    524288        // per-batch output length = SEQ*HOP
#define NPAD    1088          // padded N (17 * 64)

// GEMM tiling
#define BMg     128
#define BNg     64
#define BKg     32
#define NCHUNK  (DIM/BKg)     // 16
#define OFF_AL  10240
#define OFF_BH  20480
#define OFF_BL  25600
#define STAGEB  30720
#define DYNSM   (2*STAGEB)    // 61440

// ---------------------------------------------------------------------------
// Device scratch (allocation-free contract)
// ---------------------------------------------------------------------------
__device__ float          g_H[(size_t)MROWS * NOUT];    // h = xW + b
__device__ float          g_F[(size_t)MROWS * NFFT];    // windowed irfft frames
__device__ unsigned short g_Ah[(size_t)MROWS * DIM];    // bf16 hi(x)
__device__ unsigned short g_Al[(size_t)MROWS * DIM];    // bf16 lo(x)
__device__ unsigned short g_Wth[(size_t)NPAD * DIM];    // bf16 hi(W^T) [n][k]
__device__ unsigned short g_Wtl[(size_t)NPAD * DIM];    // bf16 lo(W^T) [n][k]
__device__ float          g_win[NFFT];                  // hann window
__device__ float          g_win2[NFFT];                 // hann^2

// ---------------------------------------------------------------------------
// Portable PTX helpers
// ---------------------------------------------------------------------------
__device__ __forceinline__ uint32_t smem_u32(const void* p) {
    uint32_t a;
    asm("{ .reg .u64 t; cvta.to.shared.u64 t, %1; cvt.u32.u64 %0, t; }"
        : "=r"(a) : "l"(p));
    return a;
}
__device__ __forceinline__ void cp16(uint32_t dst, const void* src) {
    asm volatile("cp.async.cg.shared.global [%0], [%1], 16;"
                 :: "r"(dst), "l"(src) : "memory");
}
#define CP_COMMIT() asm volatile("cp.async.commit_group;" ::: "memory")
#define CP_WAIT1()  asm volatile("cp.async.wait_group 1;" ::: "memory")

__device__ __forceinline__ void mma16816(float* c, const uint32_t* a, const uint32_t* b) {
    asm volatile(
        "mma.sync.aligned.m16n8k16.row.col.f32.bf16.bf16.f32 "
        "{%0,%1,%2,%3}, {%4,%5,%6,%7}, {%8,%9}, {%0,%1,%2,%3};"
        : "+f"(c[0]), "+f"(c[1]), "+f"(c[2]), "+f"(c[3])
        : "r"(a[0]), "r"(a[1]), "r"(a[2]), "r"(a[3]), "r"(b[0]), "r"(b[1]));
}

// ---------------------------------------------------------------------------
// Prep kernels
// ---------------------------------------------------------------------------
__device__ __forceinline__ void split_bf16(float x, unsigned short& h, unsigned short& l) {
    __nv_bfloat16 bh = __float2bfloat16(x);
    float r = x - __bfloat162float(bh);
    __nv_bfloat16 bl = __float2bfloat16(r);
    h = *reinterpret_cast<unsigned short*>(&bh);
    l = *reinterpret_cast<unsigned short*>(&bl);
}

__global__ __launch_bounds__(256) void convert_x_kernel(const float* __restrict__ x)
{
    size_t v = (size_t)blockIdx.x * 256 + threadIdx.x;
    float4 a = *reinterpret_cast<const float4*>(x + v * 4);
    unsigned short h0,l0,h1,l1,h2,l2,h3,l3;
    split_bf16(a.x, h0, l0); split_bf16(a.y, h1, l1);
    split_bf16(a.z, h2, l2); split_bf16(a.w, h3, l3);
    uint2 hv = make_uint2((uint32_t)h0 | ((uint32_t)h1 << 16), (uint32_t)h2 | ((uint32_t)h3 << 16));
    uint2 lv = make_uint2((uint32_t)l0 | ((uint32_t)l1 << 16), (uint32_t)l2 | ((uint32_t)l3 << 16));
    *reinterpret_cast<uint2*>(g_Ah + v * 4) = hv;
    *reinterpret_cast<uint2*>(g_Al + v * 4) = lv;
}

__global__ __launch_bounds__(256) void convert_w_kernel(const float* __restrict__ W)
{
    size_t v = (size_t)blockIdx.x * 256 + threadIdx.x;
    int n = (int)(v >> 7);
    int k4 = ((int)v & 127) * 4;
    unsigned short h[4], l[4];
#pragma unroll
    for (int j = 0; j < 4; j++) {
        float w = (n < NOUT) ? W[(size_t)(k4 + j) * NOUT + n] : 0.0f;
        split_bf16(w, h[j], l[j]);
    }
    uint2 hv = make_uint2((uint32_t)h[0] | ((uint32_t)h[1] << 16), (uint32_t)h[2] | ((uint32_t)h[3] << 16));
    uint2 lv = make_uint2((uint32_t)l[0] | ((uint32_t)l[1] << 16), (uint32_t)l[2] | ((uint32_t)l[3] << 16));
    *reinterpret_cast<uint2*>(g_Wth + (size_t)n * DIM + k4) = hv;
    *reinterpret_cast<uint2*>(g_Wtl + (size_t)n * DIM + k4) = lv;
}

__global__ __launch_bounds__(256) void window_kernel()
{
    int n = blockIdx.x * 256 + threadIdx.x;   // 0..1023
    float w = 0.5f * (1.0f - cosf(6.283185307179586476e0f * (float)n / 1024.0f));
    g_win[n]  = w;
    g_win2[n] = w * w;
}

// ---------------------------------------------------------------------------
// mma.sync bf16x3 GEMM (unchanged from R4)
// ---------------------------------------------------------------------------
__device__ __forceinline__ void load_stage(char* smem, int s, int kc, int tid,
                                           int m0, int n0, uint32_t smb)
{
    const uint32_t sb = smb + s * STAGEB;
    const int kk = kc * BKg;
#pragma unroll
    for (int i = 0; i < 2; i++) {
        int id = tid + i * 256;
        int row = id >> 2, c = id & 3;
        size_t goff = (size_t)(m0 + row) * DIM + kk + c * 8;
        cp16(sb + row * 80 + c * 16,           g_Ah + goff);
        cp16(sb + OFF_AL + row * 80 + c * 16,  g_Al + goff);
    }
    {
        int row = tid >> 2, c = tid & 3;
        size_t goff = (size_t)(n0 + row) * DIM + kk + c * 8;
        cp16(sb + OFF_BH + row * 80 + c * 16,  g_Wth + goff);
        cp16(sb + OFF_BL + row * 80 + c * 16,  g_Wtl + goff);
    }
}

__global__ __launch_bounds__(256) void gemm_mma_kernel(const float* __restrict__ bias)
{
    extern __shared__ char sm[];
    const int tid  = threadIdx.x;
    const int n0   = blockIdx.x * BNg;
    const int m0   = blockIdx.y * BMg;
    const int wid  = tid >> 5, lane = tid & 31;
    const int g    = lane >> 2, t = lane & 3;
    const int wM   = (wid & 3) * 32;
    const int wN   = (wid >> 2) * 32;
    const uint32_t smb = smem_u32(sm);

    float acc[2][4][4];
#pragma unroll
    for (int i = 0; i < 2; i++)
#pragma unroll
        for (int j = 0; j < 4; j++)
#pragma unroll
            for (int q = 0; q < 4; q++) acc[i][j][q] = 0.f;

    load_stage(sm, 0, 0, tid, m0, n0, smb);
    CP_COMMIT();

    for (int kc = 0; kc < NCHUNK; kc++) {
        if (kc + 1 < NCHUNK) load_stage(sm, (kc + 1) & 1, kc + 1, tid, m0, n0, smb);
        CP_COMMIT();
        CP_WAIT1();
        __syncthreads();

        char* stg = sm + (kc & 1) * STAGEB;
#pragma unroll
        for (int ks = 0; ks < 2; ks++) {
            const int kb = ks * 16;
            uint32_t ah[2][4], al[2][4], bh[4][2], bl[4][2];
#pragma unroll
            for (int mf = 0; mf < 2; mf++) {
                int rb = wM + mf * 16;
                ah[mf][0] = *(const uint32_t*)(stg + (rb + g    ) * 80 + (kb + t * 2    ) * 2);
                ah[mf][1] = *(const uint32_t*)(stg + (rb + g + 8) * 80 + (kb + t * 2    ) * 2);
                ah[mf][2] = *(const uint32_t*)(stg + (rb + g    ) * 80 + (kb + t * 2 + 8) * 2);
                ah[mf][3] = *(const uint32_t*)(stg + (rb + g + 8) * 80 + (kb + t * 2 + 8) * 2);
            }
#pragma unroll
            for (int nf = 0; nf < 4; nf++) {
                int cb = wN + nf * 8;
                bh[nf][0] = *(const uint32_t*)(stg + OFF_BH + (cb + g) * 80 + (kb + t * 2    ) * 2);
                bh[nf][1] = *(const uint32_t*)(stg + OFF_BH + (cb + g) * 80 + (kb + t * 2 + 8) * 2);
            }
#pragma unroll
            for (int mf = 0; mf < 2; mf++)
#pragma unroll
                for (int nf = 0; nf < 4; nf++)
                    mma16816(acc[mf][nf], ah[mf], bh[nf]);

#pragma unroll
            for (int nf = 0; nf < 4; nf++) {
                int cb = wN + nf * 8;
                bl[nf][0] = *(const uint32_t*)(stg + OFF_BL + (cb + g) * 80 + (kb + t * 2    ) * 2);
                bl[nf][1] = *(const uint32_t*)(stg + OFF_BL + (cb + g) * 80 + (kb + t * 2 + 8) * 2);
            }
#pragma unroll
            for (int mf = 0; mf < 2; mf++)
#pragma unroll
                for (int nf = 0; nf < 4; nf++)
                    mma16816(acc[mf][nf], ah[mf], bl[nf]);

#pragma unroll
            for (int mf = 0; mf < 2; mf++) {
                int rb = wM + mf * 16;
                al[mf][0] = *(const uint32_t*)(stg + OFF_AL + (rb + g    ) * 80 + (kb + t * 2    ) * 2);
                al[mf][1] = *(const uint32_t*)(stg + OFF_AL + (rb + g + 8) * 80 + (kb + t * 2    ) * 2);
                al[mf][2] = *(const uint32_t*)(stg + OFF_AL + (rb + g    ) * 80 + (kb + t * 2 + 8) * 2);
                al[mf][3] = *(const uint32_t*)(stg + OFF_AL + (rb + g + 8) * 80 + (kb + t * 2 + 8) * 2);
            }
#pragma unroll
            for (int mf = 0; mf < 2; mf++)
#pragma unroll
                for (int nf = 0; nf < 4; nf++)
                    mma16816(acc[mf][nf], al[mf], bh[nf]);
        }
        __syncthreads();
    }

#pragma unroll
    for (int nf = 0; nf < 4; nf++) {
        int col = n0 + wN + nf * 8 + t * 2;
        if (col < NOUT) {
            float b0 = bias[col], b1 = bias[col + 1];
#pragma unroll
            for (int mf = 0; mf < 2; mf++) {
                int r0 = m0 + wM + mf * 16 + g;
                float2 v0 = make_float2(acc[mf][nf][0] + b0, acc[mf][nf][1] + b1);
                float2 v1 = make_float2(acc[mf][nf][2] + b0, acc[mf][nf][3] + b1);
                *reinterpret_cast<float2*>(g_H + (size_t)r0 * NOUT + col) = v0;
                *reinterpret_cast<float2*>(g_H + (size_t)(r0 + 8) * NOUT + col) = v1;
            }
        }
    }
}

// ---------------------------------------------------------------------------
// Radix-8 register FFT kernel: 4 frames / 256-thread block, 64 threads/frame.
// ---------------------------------------------------------------------------
struct cf { float x, y; };
__device__ __forceinline__ cf cmul(cf a, cf b){ cf r; r.x=a.x*b.x-a.y*b.y; r.y=a.x*b.y+a.y*b.x; return r; }
__device__ __forceinline__ cf cadd(cf a, cf b){ cf r; r.x=a.x+b.x; r.y=a.y+b.y; return r; }
__device__ __forceinline__ cf csub(cf a, cf b){ cf r; r.x=a.x-b.x; r.y=a.y-b.y; return r; }
__device__ __forceinline__ cf crotp(cf a){ cf r; r.x=-a.y; r.y=a.x; return r; }   // *(+i)

// out[n] = sum_j v[j] e^{+2pi i n j / 8}; natural-order in/out
__device__ __forceinline__ void bfly8(cf v[8]) {
    cf b0=v[0], b1=v[4], b2=v[2], b3=v[6], b4=v[1], b5=v[5], b6=v[3], b7=v[7];
    cf t;
    t=b1; b1=csub(b0,t); b0=cadd(b0,t);
    t=b3; b3=csub(b2,t); b2=cadd(b2,t);
    t=b5; b5=csub(b4,t); b4=cadd(b4,t);
    t=b7; b7=csub(b6,t); b6=cadd(b6,t);
    t=b2;        b2=csub(b0,t); b0=cadd(b0,t);
    t=crotp(b3); b3=csub(b1,t); b1=cadd(b1,t);
    t=b6;        b6=csub(b4,t); b4=cadd(b4,t);
    t=crotp(b7); b7=csub(b5,t); b5=cadd(b5,t);
    const float C = 0.70710678118654752440f;
    cf w1; w1.x=C;  w1.y=C;
    cf w3; w3.x=-C; w3.y=C;
    t=b4;          v[4]=csub(b0,t); v[0]=cadd(b0,t);
    t=cmul(b5,w1); v[5]=csub(b1,t); v[1]=cadd(b1,t);
    t=crotp(b6);   v[6]=csub(b2,t); v[2]=cadd(b2,t);
    t=cmul(b7,w3); v[7]=csub(b3,t); v[3]=cadd(b3,t);
}

#define ZP(i) ((i) + ((i) >> 5))   // skewed smem index: 512 -> 528 slots

__global__ __launch_bounds__(256) void fft_kernel()
{
    __shared__ float sr[4][513], si[4][513];
    __shared__ float zr[4][528], zi[4][528];

    const int tid = threadIdx.x;
    const int fl  = tid >> 6;        // frame within block (0..3)
    const int lt  = tid & 63;        // lane within frame
    const int f   = blockIdx.x * 4 + fl;
    const float* __restrict__ h = g_H + (size_t)f * NOUT;

    float* Sr = sr[fl]; float* Si = si[fl];
    float* Zr = zr[fl]; float* Zi = zi[fl];

    // A) nonlinearity: S_k = min(exp(h_k),100) * e^{i p_k}
    for (int k = lt; k < NBINS; k += 64) {
        float mag = fminf(__expf(h[k]), 100.0f);
        float p = h[NBINS + k];
        float s, c;
        __sincosf(p, &s, &c);
        Sr[k] = mag * c;
        Si[k] = mag * s;
    }
    __syncthreads();

    // B) pack half-spectrum into 512-pt complex sequence Z (natural order)
    const float ang = 6.283185307179586476e0f / 1024.0f;
    for (int k = lt; k < 512; k += 64) {
        float R, I;
        if (k == 0) {
            R = 0.5f * (Sr[0] + Sr[512]);
            I = 0.5f * (Sr[0] - Sr[512]);
        } else {
            float ar = Sr[k],       ai = Si[k];
            float br = Sr[512 - k], bi = Si[512 - k];
            float Er = 0.5f * (ar + br), Ei = 0.5f * (ai - bi);
            float Dr = 0.5f * (ar - br), Di = 0.5f * (ai + bi);
            float s, c;
            __sincosf(ang * (float)k, &s, &c);
            float Or = Dr * c - Di * s;
            float Oi = Dr * s + Di * c;
            R = Er - Oi;
            I = Ei + Or;
        }
        Zr[ZP(k)] = R;
        Zi[ZP(k)] = I;
    }
    __syncthreads();

    cf v[8];

    // C) stage 1: digit-reversed gather, bfly8, write contiguous
    {
        int base = (lt & 7) * 8 + (lt >> 3);
#pragma unroll
        for (int m = 0; m < 8; m++) {
            int idx = m * 64 + base;
            v[m].x = Zr[ZP(idx)]; v[m].y = Zi[ZP(idx)];
        }
        bfly8(v);
        __syncthreads();
#pragma unroll
        for (int m = 0; m < 8; m++) {
            int idx = 8 * lt + m;
            Zr[ZP(idx)] = v[m].x; Zi[ZP(idx)] = v[m].y;
        }
    }
    __syncthreads();

    // D) stage 2: groups of 64, twiddle W64^{p*j}, bfly8
    {
        int p  = lt & 7;
        int Gp = (lt >> 3) * 64 + p;
#pragma unroll
        for (int j = 0; j < 8; j++) {
            int idx = Gp + 8 * j;
            v[j].x = Zr[ZP(idx)]; v[j].y = Zi[ZP(idx)];
        }
        float s, c;
        sincosf(6.283185307179586476e0f * (float)p / 64.0f, &s, &c);
        cf w1; w1.x = c; w1.y = s;
        cf w;  w.x = 1.f; w.y = 0.f;
#pragma unroll
        for (int j = 1; j < 8; j++) {
            w = cmul(w, w1);
            v[j] = cmul(v[j], w);
        }
        bfly8(v);
        __syncthreads();
#pragma unroll
        for (int j = 0; j < 8; j++) {
            int idx = Gp + 8 * j;
            Zr[ZP(idx)] = v[j].x; Zi[ZP(idx)] = v[j].y;
        }
    }
    __syncthreads();

    // E) stage 3: stride-64 butterflies, twiddle W512^{lt*j}, then direct
    //    windowed store: x[2m]=Re z_m, x[2m+1]=Im z_m (m = lt + 64j)
    {
#pragma unroll
        for (int j = 0; j < 8; j++) {
            int idx = lt + 64 * j;
            v[j].x = Zr[ZP(idx)]; v[j].y = Zi[ZP(idx)];
        }
        float s, c;
        sincosf(6.283185307179586476e0f * (float)lt / 512.0f, &s, &c);
        cf w1; w1.x = c; w1.y = s;
        cf w;  w.x = 1.f; w.y = 0.f;
#pragma unroll
        for (int j = 1; j < 8; j++) {
            w = cmul(w, w1);
            v[j] = cmul(v[j], w);
        }
        bfly8(v);

        float* __restrict__ Fo = g_F + (size_t)f * NFFT;
        const float inv = 1.0f / 512.0f;
#pragma unroll
        for (int j = 0; j < 8; j++) {
            int m = lt + 64 * j;
            float2 wv = *reinterpret_cast<const float2*>(g_win + 2 * m);
            float2 o;
            o.x = v[j].x * inv * wv.x;
            o.y = v[j].y * inv * wv.y;
            *reinterpret_cast<float2*>(Fo + 2 * m) = o;
        }
    }
}

// ---------------------------------------------------------------------------
// Overlap-add + env normalization + trim (table-driven env)
// ---------------------------------------------------------------------------
__global__ __launch_bounds__(256) void ola_kernel(float* __restrict__ out)
{
    int o = blockIdx.x * 256 + threadIdx.x;
    if (o >= OUTB) return;
    int b = blockIdx.y;
    int t = o + PADQ;

    int jhi = min(t >> 8, SEQ - 1);
    int jlo = (t - 768) >> 8;
    if (jlo < 0) jlo = 0;

    float acc = 0.f, env = 0.f;
    for (int j = jlo; j <= jhi; j++) {
        int n = t - (j << 8);
        acc += g_F[((size_t)(b * SEQ + j) << 10) + n];
        env += g_win2[n];
    }
    out[(size_t)b * OUTB + o] = acc / env;
}

// ---------------------------------------------------------------------------
extern "C" void kernel_launch(void* const* d_in, const int* in_sizes, int n_in,
                              void* d_out, int out_size)
{
    (void)in_sizes; (void)n_in; (void)out_size;
    const float* x    = (const float*)d_in[0];
    const float* Wm   = (const float*)d_in[1];
    const float* bias = (const float*)d_in[2];
    float* out = (float*)d_out;

    cudaFuncSetAttribute(gemm_mma_kernel, cudaFuncAttributeMaxDynamicSharedMemorySize, DYNSM);

    window_kernel<<<4, 256>>>();
    convert_x_kernel<<<(MROWS * DIM) / (256 * 4), 256>>>(x);
    convert_w_kernel<<<(NPAD * (DIM / 4)) / 256, 256>>>(Wm);

    dim3 ggrid(NPAD / BNg, MROWS / BMg);   // (17, 128)
    gemm_mma_kernel<<<ggrid, 256, DYNSM>>>(bias);

    fft_kernel<<<MROWS / 4, 256>>>();

    dim3 ogrid(OUTB / 256, BATCH);
    ola_kernel<<<ogrid, 256>>>(out);
}

// round 6
// speedup vs baseline: 2.2339x; 1.0473x over previous
#include <cuda_runtime.h>
#include <cuda_bf16.h>
#include <cstdint>

// ---------------------------------------------------------------------------
// Problem shape constants
// ---------------------------------------------------------------------------
#define BATCH   8
#define SEQ     2048
#define DIM     512
#define NOUT    1026          // N_FFT + 2
#define NBINS   513           // N_FFT/2 + 1
#define NFFT    1024
#define HOP     256
#define PADQ    384           // (WIN_LEN - HOP)/2
#define MROWS   (BATCH*SEQ)   // 16384
#define OUTB    524288        // per-batch output length = SEQ*HOP
#define NPAD    1088          // padded N (17 * 64)

// GEMM tiling
#define BMg     128
#define BNg     64
#define BKg     32
#define NCHUNK  (DIM/BKg)     // 16
#define OFF_AL  10240
#define OFF_BH  20480
#define OFF_BL  25600
#define STAGEB  30720
#define DYNSM   (2*STAGEB)    // 61440

// ---------------------------------------------------------------------------
// Device scratch (allocation-free contract)
// ---------------------------------------------------------------------------
__device__ float          g_H[(size_t)MROWS * NOUT];    // h = xW + b
__device__ float          g_F[(size_t)MROWS * NFFT];    // windowed irfft frames
__device__ unsigned short g_Ah[(size_t)MROWS * DIM];    // bf16 hi(x)
__device__ unsigned short g_Al[(size_t)MROWS * DIM];    // bf16 lo(x)
__device__ unsigned short g_Wth[(size_t)NPAD * DIM];    // bf16 hi(W^T) [n][k]
__device__ unsigned short g_Wtl[(size_t)NPAD * DIM];    // bf16 lo(W^T) [n][k]
__device__ float          g_win[NFFT];                  // hann window
__device__ float          g_win2[NFFT];                 // hann^2

// ---------------------------------------------------------------------------
// Portable PTX helpers
// ---------------------------------------------------------------------------
__device__ __forceinline__ uint32_t smem_u32(const void* p) {
    uint32_t a;
    asm("{ .reg .u64 t; cvta.to.shared.u64 t, %1; cvt.u32.u64 %0, t; }"
        : "=r"(a) : "l"(p));
    return a;
}
__device__ __forceinline__ void cp16(uint32_t dst, const void* src) {
    asm volatile("cp.async.cg.shared.global [%0], [%1], 16;"
                 :: "r"(dst), "l"(src) : "memory");
}
#define CP_COMMIT() asm volatile("cp.async.commit_group;" ::: "memory")
#define CP_WAIT1()  asm volatile("cp.async.wait_group 1;" ::: "memory")

__device__ __forceinline__ void mma16816(float* c, const uint32_t* a, const uint32_t* b) {
    asm volatile(
        "mma.sync.aligned.m16n8k16.row.col.f32.bf16.bf16.f32 "
        "{%0,%1,%2,%3}, {%4,%5,%6,%7}, {%8,%9}, {%0,%1,%2,%3};"
        : "+f"(c[0]), "+f"(c[1]), "+f"(c[2]), "+f"(c[3])
        : "r"(a[0]), "r"(a[1]), "r"(a[2]), "r"(a[3]), "r"(b[0]), "r"(b[1]));
}
__device__ __forceinline__ void ldsm_x4(uint32_t& r0, uint32_t& r1, uint32_t& r2,
                                        uint32_t& r3, uint32_t addr) {
    asm volatile("ldmatrix.sync.aligned.m8n8.x4.shared.b16 {%0,%1,%2,%3}, [%4];"
                 : "=r"(r0), "=r"(r1), "=r"(r2), "=r"(r3) : "r"(addr));
}

// ---------------------------------------------------------------------------
// Prep kernels
// ---------------------------------------------------------------------------
__device__ __forceinline__ void split_bf16(float x, unsigned short& h, unsigned short& l) {
    __nv_bfloat16 bh = __float2bfloat16(x);
    float r = x - __bfloat162float(bh);
    __nv_bfloat16 bl = __float2bfloat16(r);
    h = *reinterpret_cast<unsigned short*>(&bh);
    l = *reinterpret_cast<unsigned short*>(&bl);
}

__global__ __launch_bounds__(256) void convert_x_kernel(const float* __restrict__ x)
{
    size_t v = (size_t)blockIdx.x * 256 + threadIdx.x;
    float4 a = *reinterpret_cast<const float4*>(x + v * 4);
    unsigned short h0,l0,h1,l1,h2,l2,h3,l3;
    split_bf16(a.x, h0, l0); split_bf16(a.y, h1, l1);
    split_bf16(a.z, h2, l2); split_bf16(a.w, h3, l3);
    uint2 hv = make_uint2((uint32_t)h0 | ((uint32_t)h1 << 16), (uint32_t)h2 | ((uint32_t)h3 << 16));
    uint2 lv = make_uint2((uint32_t)l0 | ((uint32_t)l1 << 16), (uint32_t)l2 | ((uint32_t)l3 << 16));
    *reinterpret_cast<uint2*>(g_Ah + v * 4) = hv;
    *reinterpret_cast<uint2*>(g_Al + v * 4) = lv;
}

__global__ __launch_bounds__(256) void convert_w_kernel(const float* __restrict__ W)
{
    size_t v = (size_t)blockIdx.x * 256 + threadIdx.x;
    int n = (int)(v >> 7);
    int k4 = ((int)v & 127) * 4;
    unsigned short h[4], l[4];
#pragma unroll
    for (int j = 0; j < 4; j++) {
        float w = (n < NOUT) ? W[(size_t)(k4 + j) * NOUT + n] : 0.0f;
        split_bf16(w, h[j], l[j]);
    }
    uint2 hv = make_uint2((uint32_t)h[0] | ((uint32_t)h[1] << 16), (uint32_t)h[2] | ((uint32_t)h[3] << 16));
    uint2 lv = make_uint2((uint32_t)l[0] | ((uint32_t)l[1] << 16), (uint32_t)l[2] | ((uint32_t)l[3] << 16));
    *reinterpret_cast<uint2*>(g_Wth + (size_t)n * DIM + k4) = hv;
    *reinterpret_cast<uint2*>(g_Wtl + (size_t)n * DIM + k4) = lv;
}

__global__ __launch_bounds__(256) void window_kernel()
{
    int n = blockIdx.x * 256 + threadIdx.x;   // 0..1023
    float w = 0.5f * (1.0f - cosf(6.283185307179586476e0f * (float)n / 1024.0f));
    g_win[n]  = w;
    g_win2[n] = w * w;
}

// ---------------------------------------------------------------------------
// mma.sync bf16x3 GEMM with ldmatrix fragment loads
// ---------------------------------------------------------------------------
__device__ __forceinline__ void load_stage(int s, int kc, int tid,
                                           int m0, int n0, uint32_t smb)
{
    const uint32_t sb = smb + s * STAGEB;
    const int kk = kc * BKg;
#pragma unroll
    for (int i = 0; i < 2; i++) {
        int id = tid + i * 256;
        int row = id >> 2, c = id & 3;
        size_t goff = (size_t)(m0 + row) * DIM + kk + c * 8;
        cp16(sb + row * 80 + c * 16,           g_Ah + goff);
        cp16(sb + OFF_AL + row * 80 + c * 16,  g_Al + goff);
    }
    {
        int row = tid >> 2, c = tid & 3;
        size_t goff = (size_t)(n0 + row) * DIM + kk + c * 8;
        cp16(sb + OFF_BH + row * 80 + c * 16,  g_Wth + goff);
        cp16(sb + OFF_BL + row * 80 + c * 16,  g_Wtl + goff);
    }
}

__global__ __launch_bounds__(256) void gemm_mma_kernel(const float* __restrict__ bias)
{
    extern __shared__ char sm[];
    const int tid  = threadIdx.x;
    const int n0   = blockIdx.x * BNg;
    const int m0   = blockIdx.y * BMg;
    const int wid  = tid >> 5, lane = tid & 31;
    const int g    = lane >> 2, t = lane & 3;
    const int wM   = (wid & 3) * 32;
    const int wN   = (wid >> 2) * 32;
    const uint32_t smb = smem_u32(sm);

    // ldmatrix address components (per lane)
    const int mat = lane >> 3;           // matrix index 0..3
    const int mr  = lane & 7;            // row within matrix
    // A: matrices (m0-7,k0-7),(m8-15,k0-7),(m0-7,k8-15),(m8-15,k8-15)
    const int aRow = ((mat & 1) << 3) + mr;       // + wM + mf*16
    const int aK   = (mat >> 1) << 3;             // + kb
    // B: matrices (n0-7,k0-7),(n0-7,k8-15),(n8-15,k0-7),(n8-15,k8-15)
    const int bRow = ((mat >> 1) << 3) + mr;      // + wN + np*16
    const int bK   = (mat & 1) << 3;              // + kb

    float acc[2][4][4];
#pragma unroll
    for (int i = 0; i < 2; i++)
#pragma unroll
        for (int j = 0; j < 4; j++)
#pragma unroll
            for (int q = 0; q < 4; q++) acc[i][j][q] = 0.f;

    load_stage(0, 0, tid, m0, n0, smb);
    CP_COMMIT();

    for (int kc = 0; kc < NCHUNK; kc++) {
        if (kc + 1 < NCHUNK) load_stage((kc + 1) & 1, kc + 1, tid, m0, n0, smb);
        CP_COMMIT();
        CP_WAIT1();
        __syncthreads();

        const uint32_t stg = smb + (kc & 1) * STAGEB;
#pragma unroll
        for (int ks = 0; ks < 2; ks++) {
            const int kb = ks * 16;
            uint32_t ah[2][4], al[2][4], bh[4][2], bl[4][2];

            // A hi fragments (2 x4-ldmatrix)
#pragma unroll
            for (int mf = 0; mf < 2; mf++) {
                uint32_t addr = stg + (wM + mf * 16 + aRow) * 80 + (kb + aK) * 2;
                ldsm_x4(ah[mf][0], ah[mf][1], ah[mf][2], ah[mf][3], addr);
            }
            // B hi fragments (2 x4-ldmatrix -> 4 nf fragments)
#pragma unroll
            for (int np = 0; np < 2; np++) {
                uint32_t addr = stg + OFF_BH + (wN + np * 16 + bRow) * 80 + (kb + bK) * 2;
                ldsm_x4(bh[2*np][0], bh[2*np][1], bh[2*np+1][0], bh[2*np+1][1], addr);
            }
#pragma unroll
            for (int mf = 0; mf < 2; mf++)
#pragma unroll
                for (int nf = 0; nf < 4; nf++)
                    mma16816(acc[mf][nf], ah[mf], bh[nf]);

            // B lo fragments
#pragma unroll
            for (int np = 0; np < 2; np++) {
                uint32_t addr = stg + OFF_BL + (wN + np * 16 + bRow) * 80 + (kb + bK) * 2;
                ldsm_x4(bl[2*np][0], bl[2*np][1], bl[2*np+1][0], bl[2*np+1][1], addr);
            }
#pragma unroll
            for (int mf = 0; mf < 2; mf++)
#pragma unroll
                for (int nf = 0; nf < 4; nf++)
                    mma16816(acc[mf][nf], ah[mf], bl[nf]);

            // A lo fragments
#pragma unroll
            for (int mf = 0; mf < 2; mf++) {
                uint32_t addr = stg + OFF_AL + (wM + mf * 16 + aRow) * 80 + (kb + aK) * 2;
                ldsm_x4(al[mf][0], al[mf][1], al[mf][2], al[mf][3], addr);
            }
#pragma unroll
            for (int mf = 0; mf < 2; mf++)
#pragma unroll
                for (int nf = 0; nf < 4; nf++)
                    mma16816(acc[mf][nf], al[mf], bh[nf]);
        }
        __syncthreads();
    }

#pragma unroll
    for (int nf = 0; nf < 4; nf++) {
        int col = n0 + wN + nf * 8 + t * 2;
        if (col < NOUT) {
            float b0 = bias[col], b1 = bias[col + 1];
#pragma unroll
            for (int mf = 0; mf < 2; mf++) {
                int r0 = m0 + wM + mf * 16 + g;
                float2 v0 = make_float2(acc[mf][nf][0] + b0, acc[mf][nf][1] + b1);
                float2 v1 = make_float2(acc[mf][nf][2] + b0, acc[mf][nf][3] + b1);
                *reinterpret_cast<float2*>(g_H + (size_t)r0 * NOUT + col) = v0;
                *reinterpret_cast<float2*>(g_H + (size_t)(r0 + 8) * NOUT + col) = v1;
            }
        }
    }
}

// ---------------------------------------------------------------------------
// Radix-8 register FFT kernel: 4 frames / 256-thread block, 64 threads/frame.
// ---------------------------------------------------------------------------
struct cf { float x, y; };
__device__ __forceinline__ cf cmul(cf a, cf b){ cf r; r.x=a.x*b.x-a.y*b.y; r.y=a.x*b.y+a.y*b.x; return r; }
__device__ __forceinline__ cf cadd(cf a, cf b){ cf r; r.x=a.x+b.x; r.y=a.y+b.y; return r; }
__device__ __forceinline__ cf csub(cf a, cf b){ cf r; r.x=a.x-b.x; r.y=a.y-b.y; return r; }
__device__ __forceinline__ cf crotp(cf a){ cf r; r.x=-a.y; r.y=a.x; return r; }   // *(+i)

__device__ __forceinline__ void bfly8(cf v[8]) {
    cf b0=v[0], b1=v[4], b2=v[2], b3=v[6], b4=v[1], b5=v[5], b6=v[3], b7=v[7];
    cf t;
    t=b1; b1=csub(b0,t); b0=cadd(b0,t);
    t=b3; b3=csub(b2,t); b2=cadd(b2,t);
    t=b5; b5=csub(b4,t); b4=cadd(b4,t);
    t=b7; b7=csub(b6,t); b6=cadd(b6,t);
    t=b2;        b2=csub(b0,t); b0=cadd(b0,t);
    t=crotp(b3); b3=csub(b1,t); b1=cadd(b1,t);
    t=b6;        b6=csub(b4,t); b4=cadd(b4,t);
    t=crotp(b7); b7=csub(b5,t); b5=cadd(b5,t);
    const float C = 0.70710678118654752440f;
    cf w1; w1.x=C;  w1.y=C;
    cf w3; w3.x=-C; w3.y=C;
    t=b4;          v[4]=csub(b0,t); v[0]=cadd(b0,t);
    t=cmul(b5,w1); v[5]=csub(b1,t); v[1]=cadd(b1,t);
    t=crotp(b6);   v[6]=csub(b2,t); v[2]=cadd(b2,t);
    t=cmul(b7,w3); v[7]=csub(b3,t); v[3]=cadd(b3,t);
}

#define ZP(i) ((i) + ((i) >> 5))   // skewed smem index: 512 -> 528 slots

__global__ __launch_bounds__(256) void fft_kernel()
{
    __shared__ float sr[4][513], si[4][513];
    __shared__ float zr[4][528], zi[4][528];

    const int tid = threadIdx.x;
    const int fl  = tid >> 6;
    const int lt  = tid & 63;
    const int f   = blockIdx.x * 4 + fl;
    const float* __restrict__ h = g_H + (size_t)f * NOUT;

    float* Sr = sr[fl]; float* Si = si[fl];
    float* Zr = zr[fl]; float* Zi = zi[fl];

    for (int k = lt; k < NBINS; k += 64) {
        float mag = fminf(__expf(h[k]), 100.0f);
        float p = h[NBINS + k];
        float s, c;
        __sincosf(p, &s, &c);
        Sr[k] = mag * c;
        Si[k] = mag * s;
    }
    __syncthreads();

    const float ang = 6.283185307179586476e0f / 1024.0f;
    for (int k = lt; k < 512; k += 64) {
        float R, I;
        if (k == 0) {
            R = 0.5f * (Sr[0] + Sr[512]);
            I = 0.5f * (Sr[0] - Sr[512]);
        } else {
            float ar = Sr[k],       ai = Si[k];
            float br = Sr[512 - k], bi = Si[512 - k];
            float Er = 0.5f * (ar + br), Ei = 0.5f * (ai - bi);
            float Dr = 0.5f * (ar - br), Di = 0.5f * (ai + bi);
            float s, c;
            __sincosf(ang * (float)k, &s, &c);
            float Or = Dr * c - Di * s;
            float Oi = Dr * s + Di * c;
            R = Er - Oi;
            I = Ei + Or;
        }
        Zr[ZP(k)] = R;
        Zi[ZP(k)] = I;
    }
    __syncthreads();

    cf v[8];

    {
        int base = (lt & 7) * 8 + (lt >> 3);
#pragma unroll
        for (int m = 0; m < 8; m++) {
            int idx = m * 64 + base;
            v[m].x = Zr[ZP(idx)]; v[m].y = Zi[ZP(idx)];
        }
        bfly8(v);
        __syncthreads();
#pragma unroll
        for (int m = 0; m < 8; m++) {
            int idx = 8 * lt + m;
            Zr[ZP(idx)] = v[m].x; Zi[ZP(idx)] = v[m].y;
        }
    }
    __syncthreads();

    {
        int p  = lt & 7;
        int Gp = (lt >> 3) * 64 + p;
#pragma unroll
        for (int j = 0; j < 8; j++) {
            int idx = Gp + 8 * j;
            v[j].x = Zr[ZP(idx)]; v[j].y = Zi[ZP(idx)];
        }
        float s, c;
        sincosf(6.283185307179586476e0f * (float)p / 64.0f, &s, &c);
        cf w1; w1.x = c; w1.y = s;
        cf w;  w.x = 1.f; w.y = 0.f;
#pragma unroll
        for (int j = 1; j < 8; j++) {
            w = cmul(w, w1);
            v[j] = cmul(v[j], w);
        }
        bfly8(v);
        __syncthreads();
#pragma unroll
        for (int j = 0; j < 8; j++) {
            int idx = Gp + 8 * j;
            Zr[ZP(idx)] = v[j].x; Zi[ZP(idx)] = v[j].y;
        }
    }
    __syncthreads();

    {
#pragma unroll
        for (int j = 0; j < 8; j++) {
            int idx = lt + 64 * j;
            v[j].x = Zr[ZP(idx)]; v[j].y = Zi[ZP(idx)];
        }
        float s, c;
        sincosf(6.283185307179586476e0f * (float)lt / 512.0f, &s, &c);
        cf w1; w1.x = c; w1.y = s;
        cf w;  w.x = 1.f; w.y = 0.f;
#pragma unroll
        for (int j = 1; j < 8; j++) {
            w = cmul(w, w1);
            v[j] = cmul(v[j], w);
        }
        bfly8(v);

        float* __restrict__ Fo = g_F + (size_t)f * NFFT;
        const float inv = 1.0f / 512.0f;
#pragma unroll
        for (int j = 0; j < 8; j++) {
            int m = lt + 64 * j;
            float2 wv = *reinterpret_cast<const float2*>(g_win + 2 * m);
            float2 o;
            o.x = v[j].x * inv * wv.x;
            o.y = v[j].y * inv * wv.y;
            *reinterpret_cast<float2*>(Fo + 2 * m) = o;
        }
    }
}

// ---------------------------------------------------------------------------
// Overlap-add + env normalization + trim (table-driven env)
// ---------------------------------------------------------------------------
__global__ __launch_bounds__(256) void ola_kernel(float* __restrict__ out)
{
    int o = blockIdx.x * 256 + threadIdx.x;
    if (o >= OUTB) return;
    int b = blockIdx.y;
    int t = o + PADQ;

    int jhi = min(t >> 8, SEQ - 1);
    int jlo = (t - 768) >> 8;
    if (jlo < 0) jlo = 0;

    float acc = 0.f, env = 0.f;
    for (int j = jlo; j <= jhi; j++) {
        int n = t - (j << 8);
        acc += g_F[((size_t)(b * SEQ + j) << 10) + n];
        env += g_win2[n];
    }
    out[(size_t)b * OUTB + o] = acc / env;
}

// ---------------------------------------------------------------------------
extern "C" void kernel_launch(void* const* d_in, const int* in_sizes, int n_in,
                              void* d_out, int out_size)
{
    (void)in_sizes; (void)n_in; (void)out_size;
    const float* x    = (const float*)d_in[0];
    const float* Wm   = (const float*)d_in[1];
    const float* bias = (const float*)d_in[2];
    float* out = (float*)d_out;

    cudaFuncSetAttribute(gemm_mma_kernel, cudaFuncAttributeMaxDynamicSharedMemorySize, DYNSM);

    window_kernel<<<4, 256>>>();
    convert_x_kernel<<<(MROWS * DIM) / (256 * 4), 256>>>(x);
    convert_w_kernel<<<(NPAD * (DIM / 4)) / 256, 256>>>(Wm);

    dim3 ggrid(NPAD / BNg, MROWS / BMg);   // (17, 128)
    gemm_mma_kernel<<<ggrid, 256, DYNSM>>>(bias);

    fft_kernel<<<MROWS / 4, 256>>>();

    dim3 ogrid(OUTB / 256, BATCH);
    ola_kernel<<<ogrid, 256>>>(out);
}